// round 4
// baseline (speedup 1.0000x reference)
#include <cuda_runtime.h>

#define B_ 8
#define N_ 8192
#define C_ 6
#define G_ 512
#define K_ 32

// Plain mul/add sum of squares: (a0*a0 + a1*a1) + a2*a2, contraction blocked.
// Used by FPS, which is empirically bitwise-correct on the fixed input.
__device__ __forceinline__ float sq3(float a0, float a1, float a2) {
    return __fadd_rn(__fadd_rn(__fmul_rn(a0, a0), __fmul_rn(a1, a1)),
                     __fmul_rn(a2, a2));
}

// Ascending FMA-chain sum of squares, matching XLA's fused reduce lowering:
// acc = fma(a0,a0,0) -> fma(a1,a1,acc) -> fma(a2,a2,acc).
__device__ __forceinline__ float sq3_fma(float a0, float a1, float a2) {
    float acc = __fmul_rn(a0, a0);          // == fma(a0,a0,0)
    acc = __fmaf_rn(a1, a1, acc);
    acc = __fmaf_rn(a2, a2, acc);
    return acc;
}

// ---------------------------------------------------------------------------
// FPS: one CTA per batch. 1024 threads, 8 points per thread, all point
// coords + running min-distances in registers. Verified bitwise-exact on the
// fixed benchmark input (center output passed in R2/R3) — DO NOT CHANGE.
// ---------------------------------------------------------------------------
__global__ void __launch_bounds__(1024) fps_kernel(
    const float* __restrict__ pts, float* __restrict__ center_out) {
    const int b    = blockIdx.x;
    const int tid  = threadIdx.x;
    const int lane = tid & 31;
    const int warp = tid >> 5;

    float px[8], py[8], pz[8], dist[8];
    const float* base = pts + (size_t)b * N_ * C_;
#pragma unroll
    for (int j = 0; j < 8; j++) {
        const int p = tid + (j << 10);
        const float* q = base + (size_t)p * C_;
        px[j] = q[0];
        py[j] = q[1];
        pz[j] = q[2];
        dist[j] = 1e10f;
    }

    __shared__ float s_c[3];
    __shared__ float s_val[32];
    __shared__ int   s_idx[32];
    __shared__ int   s_far;

    int far = 0;
    for (int g = 0; g < G_; g++) {
        if (tid == (far & 1023)) {
            const int j = far >> 10;
            s_c[0] = px[j];
            s_c[1] = py[j];
            s_c[2] = pz[j];
            float* co = center_out + ((size_t)b * G_ + g) * 3;
            co[0] = px[j];
            co[1] = py[j];
            co[2] = pz[j];
        }
        __syncthreads();
        const float cx = s_c[0], cy = s_c[1], cz = s_c[2];

        float bv = -1.0f;
        int   bi = 0x7fffffff;
#pragma unroll
        for (int j = 0; j < 8; j++) {
            const float dx = __fsub_rn(px[j], cx);
            const float dy = __fsub_rn(py[j], cy);
            const float dz = __fsub_rn(pz[j], cz);
            const float d  = sq3(dx, dy, dz);
            const float nd = fminf(dist[j], d);
            dist[j] = nd;
            if (nd > bv) { bv = nd; bi = tid + (j << 10); }
        }
#pragma unroll
        for (int off = 16; off; off >>= 1) {
            const float ov = __shfl_down_sync(0xffffffffu, bv, off);
            const int   oi = __shfl_down_sync(0xffffffffu, bi, off);
            if (ov > bv || (ov == bv && oi < bi)) { bv = ov; bi = oi; }
        }
        if (lane == 0) { s_val[warp] = bv; s_idx[warp] = bi; }
        __syncthreads();
        if (warp == 0) {
            float v = s_val[lane];
            int   i = s_idx[lane];
#pragma unroll
            for (int off = 16; off; off >>= 1) {
                const float ov = __shfl_down_sync(0xffffffffu, v, off);
                const int   oi = __shfl_down_sync(0xffffffffu, i, off);
                if (ov > v || (ov == v && oi < i)) { v = ov; i = oi; }
            }
            if (lane == 0) s_far = i;
        }
        __syncthreads();
        far = s_far;
    }
}

// ---------------------------------------------------------------------------
// KNN + gather + center: one CTA per (b, g) center.
// d2 = (cc + xx) - 2*dot with cc, xx AND dot all as ascending FMA chains
// (XLA fused-reduce lowering). Final combine: rn((cc+xx) - 2*dot); 2*dot is
// exact, so sub(add, mul) == fma(-2, dot, cc+xx) bitwise.
// ---------------------------------------------------------------------------
__global__ void __launch_bounds__(256) knn_kernel(
    const float* __restrict__ pts, const float* __restrict__ center_in,
    float* __restrict__ nbr_out) {
    __shared__ float s_d2[N_];
    __shared__ int   s_sel[K_];
    __shared__ float s_v[8];
    __shared__ int   s_i[8];
    __shared__ float s_ctr[3];

    const int bg   = blockIdx.x;
    const int b    = bg >> 9;  // / G_
    const int tid  = threadIdx.x;
    const int lane = tid & 31;
    const int warp = tid >> 5;

    if (tid < 3) s_ctr[tid] = center_in[(size_t)bg * 3 + tid];
    __syncthreads();
    const float c0 = s_ctr[0], c1 = s_ctr[1], c2 = s_ctr[2];
    const float cc = sq3_fma(c0, c1, c2);

    const float* base = pts + (size_t)b * N_ * C_;
    for (int n = tid; n < N_; n += 256) {
        const float* q = base + (size_t)n * C_;
        const float x0 = q[0], x1 = q[1], x2 = q[2];
        const float xx = sq3_fma(x0, x1, x2);
        // ascending FMA-chain dot
        float dot = __fmul_rn(c0, x0);
        dot = __fmaf_rn(c1, x1, dot);
        dot = __fmaf_rn(c2, x2, dot);
        s_d2[n] = __fsub_rn(__fadd_rn(cc, xx), __fmul_rn(2.0f, dot));
    }
    __syncthreads();

    const float INF = __int_as_float(0x7f800000);
    for (int k = 0; k < K_; k++) {
        float bv = INF;
        int   bi = 0x7fffffff;
#pragma unroll
        for (int i = 0; i < N_ / 256; i++) {
            const int   n = tid + i * 256;  // ascending -> strict < keeps first
            const float v = s_d2[n];
            if (v < bv) { bv = v; bi = n; }
        }
#pragma unroll
        for (int off = 16; off; off >>= 1) {
            const float ov = __shfl_down_sync(0xffffffffu, bv, off);
            const int   oi = __shfl_down_sync(0xffffffffu, bi, off);
            if (ov < bv || (ov == bv && oi < bi)) { bv = ov; bi = oi; }
        }
        if (lane == 0) { s_v[warp] = bv; s_i[warp] = bi; }
        __syncthreads();
        if (warp == 0) {
            float v = (lane < 8) ? s_v[lane] : INF;
            int   i = (lane < 8) ? s_i[lane] : 0x7fffffff;
#pragma unroll
            for (int off = 16; off; off >>= 1) {
                const float ov = __shfl_down_sync(0xffffffffu, v, off);
                const int   oi = __shfl_down_sync(0xffffffffu, i, off);
                if (ov < v || (ov == v && oi < i)) { v = ov; i = oi; }
            }
            if (lane == 0) {
                s_sel[k] = i;
                s_d2[i]  = INF;  // exclude from subsequent passes
            }
        }
        __syncthreads();
    }

    // Gather neighborhoods and center the xyz channels.
    if (tid < K_ * C_) {
        const int k = tid / C_;
        const int c = tid % C_;
        const int i = s_sel[k];
        float v = base[(size_t)i * C_ + c];
        if (c < 3) v = __fsub_rn(v, s_ctr[c]);
        nbr_out[((size_t)bg * K_ + k) * C_ + c] = v;
    }
}

extern "C" void kernel_launch(void* const* d_in, const int* in_sizes, int n_in,
                              void* d_out, int out_size) {
    const float* pts = (const float*)d_in[0];
    float* out = (float*)d_out;
    // output layout: neighborhood (B,G,K,C) flattened, then center (B,G,3)
    float* center_out = out + (size_t)B_ * G_ * K_ * C_;

    fps_kernel<<<B_, 1024>>>(pts, center_out);
    knn_kernel<<<B_ * G_, 256>>>(pts, center_out, out);
}

// round 5
// speedup vs baseline: 2.1959x; 2.1959x over previous
#include <cuda_runtime.h>

#define B_ 8
#define N_ 8192
#define C_ 6
#define G_ 512
#define K_ 32

// Plain mul/add sum of squares: (a0*a0 + a1*a1) + a2*a2, contraction blocked.
// FPS arithmetic — bitwise-verified on the fixed input. DO NOT CHANGE.
__device__ __forceinline__ float sq3(float a0, float a1, float a2) {
    return __fadd_rn(__fadd_rn(__fmul_rn(a0, a0), __fmul_rn(a1, a1)),
                     __fmul_rn(a2, a2));
}

// Ascending FMA-chain sum of squares (XLA fused-reduce lowering).
// KNN arithmetic — bitwise-verified (rel_err 0.0 in R4). DO NOT CHANGE.
__device__ __forceinline__ float sq3_fma(float a0, float a1, float a2) {
    float acc = __fmul_rn(a0, a0);
    acc = __fmaf_rn(a1, a1, acc);
    acc = __fmaf_rn(a2, a2, acc);
    return acc;
}

// ---------------------------------------------------------------------------
// FPS: one CTA per batch, 1024 threads, 8 points/thread in registers.
// Optimized control flow vs R4:
//  - centroid fetched by broadcast loads from global (L1-resident) -> no
//    owner-publish step, no extra barrier
//  - min/argmax tracked on float BITS (umin/umax, alu pipe) — bit-identical
//    to fminf/compare for non-negative floats, overlaps the fma-bound update
//  - warp argmax via redux.sync; cross-warp partials in a parity double
//    buffer; ALL warps redundantly reduce them -> ONE __syncthreads per iter
// ---------------------------------------------------------------------------
__global__ void __launch_bounds__(1024) fps_kernel(
    const float* __restrict__ pts, float* __restrict__ center_out) {
    const int b    = blockIdx.x;
    const int tid  = threadIdx.x;
    const int lane = tid & 31;
    const int warp = tid >> 5;

    float px[8], py[8], pz[8];
    unsigned du[8];
    const float* base = pts + (size_t)b * N_ * C_;
#pragma unroll
    for (int j = 0; j < 8; j++) {
        const int p = tid + (j << 10);
        const float2 xy = *(const float2*)(base + (size_t)p * C_);
        px[j] = xy.x;
        py[j] = xy.y;
        pz[j] = base[(size_t)p * C_ + 2];
        du[j] = __float_as_uint(1e10f);
    }

    __shared__ unsigned s_wv[2][32];
    __shared__ int      s_wi[2][32];

    int far = 0;
    for (int g = 0; g < G_; g++) {
        const int par = g & 1;
        // broadcast centroid load (same address across warp -> 1 wavefront)
        const float* cq = base + (size_t)far * C_;
        const float2 cxy = *(const float2*)cq;
        const float cx = cxy.x, cy = cxy.y, cz = cq[2];
        if (tid == 0) {
            float* co = center_out + ((size_t)b * G_ + g) * 3;
            co[0] = cx; co[1] = cy; co[2] = cz;
        }

        unsigned bmax = 0u;
#pragma unroll
        for (int j = 0; j < 8; j++) {
            const float dx = __fsub_rn(px[j], cx);
            const float dy = __fsub_rn(py[j], cy);
            const float dz = __fsub_rn(pz[j], cz);
            const float d  = sq3(dx, dy, dz);
            // bit-min == fminf for non-negative floats (bit-exact)
            du[j] = umin(du[j], __float_as_uint(d));
            bmax  = umax(bmax, du[j]);
        }
        // first local index attaining bmax (descending scan keeps smallest j)
        int bi = 0x7fffffff;
#pragma unroll
        for (int j = 7; j >= 0; j--)
            if (du[j] == bmax) bi = tid + (j << 10);

        // warp argmax (tie -> min index) via redux
        const unsigned wmax = __reduce_max_sync(0xffffffffu, bmax);
        const int      wmin = __reduce_min_sync(
            0xffffffffu, (bmax == wmax) ? bi : 0x7fffffff);
        if (lane == 0) { s_wv[par][warp] = wmax; s_wi[par][warp] = wmin; }
        __syncthreads();  // the only barrier per iteration

        // every warp redundantly reduces the 32 per-warp partials
        const unsigned v = s_wv[par][lane];
        const int      i = s_wi[par][lane];
        const unsigned gm = __reduce_max_sync(0xffffffffu, v);
        far = __reduce_min_sync(0xffffffffu,
                                (v == gm) ? i : 0x7fffffff);
    }
}

// ---------------------------------------------------------------------------
// KNN + gather + center: one CTA per (b, g) center.
// d2 math identical to R4 (bitwise). d2 re-encoded as sortable uint32 keys
// (sign-flip transform: monotone for ALL floats incl. negatives), so
// (key, index) ascending == top_k(-d2) order exactly.
// Selection: 64 chunk-mins, each of 32 passes touches 64 mins + one
// 128-element chunk, entirely inside warp 0 with redux (no barriers).
// ---------------------------------------------------------------------------
__global__ void __launch_bounds__(256) knn_kernel(
    const float* __restrict__ pts, const float* __restrict__ center_in,
    float* __restrict__ nbr_out) {
    __shared__ __align__(16) unsigned s_key[N_];
    __shared__ unsigned s_cmin[64];
    __shared__ int      s_sel[K_];
    __shared__ float    s_ctr[3];

    const int bg   = blockIdx.x;
    const int b    = bg >> 9;  // / G_
    const int tid  = threadIdx.x;
    const int lane = tid & 31;
    const int warp = tid >> 5;

    if (tid < 3) s_ctr[tid] = center_in[(size_t)bg * 3 + tid];
    __syncthreads();
    const float c0 = s_ctr[0], c1 = s_ctr[1], c2 = s_ctr[2];
    const float cc = sq3_fma(c0, c1, c2);

    const float* base = pts + (size_t)b * N_ * C_;
    for (int n = tid; n < N_; n += 256) {
        const float2 xy = *(const float2*)(base + (size_t)n * C_);
        const float x0 = xy.x, x1 = xy.y;
        const float x2 = base[(size_t)n * C_ + 2];
        const float xx = sq3_fma(x0, x1, x2);
        float dot = __fmul_rn(c0, x0);
        dot = __fmaf_rn(c1, x1, dot);
        dot = __fmaf_rn(c2, x2, dot);
        const float d2 = __fsub_rn(__fadd_rn(cc, xx), __fmul_rn(2.0f, dot));
        // sortable key: order(key) == order(d2) for all floats
        const unsigned bits = __float_as_uint(d2);
        s_key[n] = (bits & 0x80000000u) ? ~bits : (bits | 0x80000000u);
    }
    __syncthreads();

    // 64 chunk minima (chunks of 128 contiguous points)
    if (tid < 64) {
        const uint4* p4 = (const uint4*)(s_key + (tid << 7));
        unsigned m = 0xffffffffu;
#pragma unroll 8
        for (int j = 0; j < 32; j++) {
            const uint4 v = p4[j];
            m = umin(m, umin(umin(v.x, v.y), umin(v.z, v.w)));
        }
        s_cmin[tid] = m;
    }
    __syncthreads();

    if (warp == 0) {
        for (int k = 0; k < K_; k++) {
            const unsigned a  = s_cmin[lane];
            const unsigned bb = s_cmin[lane + 32];
            const unsigned g  = __reduce_min_sync(0xffffffffu, umin(a, bb));
            // lowest-index chunk holding the global min (index order == tie order)
            const unsigned cand =
                (a == g) ? (unsigned)lane
                         : ((bb == g) ? (unsigned)(lane + 32) : 1000u);
            const unsigned c = __reduce_min_sync(0xffffffffu, cand);

            const unsigned bi = (c << 7) + lane;
            unsigned v0 = s_key[bi];
            unsigned v1 = s_key[bi + 32];
            unsigned v2 = s_key[bi + 64];
            unsigned v3 = s_key[bi + 96];
            // first in-chunk offset attaining g (descending keeps smallest)
            unsigned off = 0x7fffffffu;
            if (v3 == g) off = 96u;
            if (v2 == g) off = 64u;
            if (v1 == g) off = 32u;
            if (v0 == g) off = 0u;
            const unsigned prel = __reduce_min_sync(
                0xffffffffu, (off == 0x7fffffffu) ? 0x7fffffffu : off + lane);
            const unsigned p = (c << 7) + prel;

            if (lane == 0) { s_sel[k] = (int)p; s_key[p] = 0xffffffffu; }
            // recompute this chunk's min with the winner poisoned (registers)
            v0 = ((unsigned)lane + 0u  == prel) ? 0xffffffffu : v0;
            v1 = ((unsigned)lane + 32u == prel) ? 0xffffffffu : v1;
            v2 = ((unsigned)lane + 64u == prel) ? 0xffffffffu : v2;
            v3 = ((unsigned)lane + 96u == prel) ? 0xffffffffu : v3;
            const unsigned nm = __reduce_min_sync(
                0xffffffffu, umin(umin(v0, v1), umin(v2, v3)));
            if (lane == 0) s_cmin[c] = nm;
            __syncwarp();
        }
    }
    __syncthreads();

    // Gather neighborhoods and center the xyz channels.
    if (tid < K_ * C_) {
        const int k = tid / C_;
        const int c = tid % C_;
        const int i = s_sel[k];
        float v = base[(size_t)i * C_ + c];
        if (c < 3) v = __fsub_rn(v, s_ctr[c]);
        nbr_out[((size_t)bg * K_ + k) * C_ + c] = v;
    }
}

extern "C" void kernel_launch(void* const* d_in, const int* in_sizes, int n_in,
                              void* d_out, int out_size) {
    const float* pts = (const float*)d_in[0];
    float* out = (float*)d_out;
    // output layout: neighborhood (B,G,K,C) flattened, then center (B,G,3)
    float* center_out = out + (size_t)B_ * G_ * K_ * C_;

    fps_kernel<<<B_, 1024>>>(pts, center_out);
    knn_kernel<<<B_ * G_, 256>>>(pts, center_out, out);
}

// round 7
// speedup vs baseline: 2.6889x; 1.2245x over previous
#include <cuda_runtime.h>

#define B_ 8
#define N_ 8192
#define C_ 6
#define G_ 512
#define K_ 32

// Plain mul/add sum of squares (FPS arithmetic — bitwise-verified).
__device__ __forceinline__ float sq3(float a0, float a1, float a2) {
    return __fadd_rn(__fadd_rn(__fmul_rn(a0, a0), __fmul_rn(a1, a1)),
                     __fmul_rn(a2, a2));
}

// Ascending FMA-chain sum of squares (KNN arithmetic — bitwise-verified).
__device__ __forceinline__ float sq3_fma(float a0, float a1, float a2) {
    float acc = __fmul_rn(a0, a0);
    acc = __fmaf_rn(a1, a1, acc);
    acc = __fmaf_rn(a2, a2, acc);
    return acc;
}

// Blackwell packed fp32x2: two independent IEEE-rn fp32 ops per instruction.
// Bit-identical to the scalar mul/add chain, half the fma-pipe instructions.
#define ADD2(o, a, b) \
    asm("add.rn.f32x2 %0, %1, %2;" : "=l"(o) : "l"(a), "l"(b))
#define MUL2(o, a, b) \
    asm("mul.rn.f32x2 %0, %1, %2;" : "=l"(o) : "l"(a), "l"(b))
#define PACK2(o, lo, hi) \
    asm("mov.b64 %0, {%1, %2};" : "=l"(o) : "f"(lo), "f"(hi))
#define UNPACK2(lo, hi, v) \
    asm("mov.b64 {%0, %1}, %2;" : "=f"(lo), "=f"(hi) : "l"(v))

// ---------------------------------------------------------------------------
// FPS: one CTA per batch, 1024 threads, 8 points/thread in registers, packed
// two-per-f32x2. Distance update d = ((x-c)^2 + (y-c)^2) + (z-c)^2 evaluated
// with mul.rn/add.rn per lane — bit-identical to the verified scalar form
// (x - c == x + (-c), negation exact). Reduction tail identical to R5.
// ---------------------------------------------------------------------------
__global__ void __launch_bounds__(1024) fps_kernel(
    const float* __restrict__ pts, float* __restrict__ center_out) {
    const int b    = blockIdx.x;
    const int tid  = threadIdx.x;
    const int lane = tid & 31;
    const int warp = tid >> 5;

    // pxv[j] packs points (tid + (2j)*1024, tid + (2j+1)*1024)
    unsigned long long pxv[4], pyv[4], pzv[4];
    unsigned du[8];
    const float* base = pts + (size_t)b * N_ * C_;
#pragma unroll
    for (int j = 0; j < 4; j++) {
        const int p0 = tid + ((2 * j) << 10);
        const int p1 = tid + ((2 * j + 1) << 10);
        const float2 a01 = *(const float2*)(base + (size_t)p0 * C_);
        const float  a2  = base[(size_t)p0 * C_ + 2];
        const float2 b01 = *(const float2*)(base + (size_t)p1 * C_);
        const float  b2  = base[(size_t)p1 * C_ + 2];
        PACK2(pxv[j], a01.x, b01.x);
        PACK2(pyv[j], a01.y, b01.y);
        PACK2(pzv[j], a2, b2);
        du[2 * j]     = __float_as_uint(1e10f);
        du[2 * j + 1] = __float_as_uint(1e10f);
    }

    __shared__ unsigned s_wv[2][32];
    __shared__ int      s_wi[2][32];

    int far = 0;
    for (int g = 0; g < G_; g++) {
        const int par = g & 1;
        const float* cq = base + (size_t)far * C_;
        const float2 cxy = *(const float2*)cq;
        const float cx = cxy.x, cy = cxy.y, cz = cq[2];
        if (tid == 0) {
            float* co = center_out + ((size_t)b * G_ + g) * 3;
            co[0] = cx; co[1] = cy; co[2] = cz;
        }
        unsigned long long ncx, ncy, ncz;
        {
            const float nx = -cx, ny = -cy, nz = -cz;
            PACK2(ncx, nx, nx);
            PACK2(ncy, ny, ny);
            PACK2(ncz, nz, nz);
        }

        unsigned bmax = 0u;
#pragma unroll
        for (int j = 0; j < 4; j++) {
            unsigned long long dx, dy, dz, mx, my, mz, s1, d;
            ADD2(dx, pxv[j], ncx);          // x + (-c) == x - c, bit-exact
            ADD2(dy, pyv[j], ncy);
            ADD2(dz, pzv[j], ncz);
            MUL2(mx, dx, dx);
            MUL2(my, dy, dy);
            MUL2(mz, dz, dz);
            ADD2(s1, mx, my);
            ADD2(d, s1, mz);
            float d0, d1;
            UNPACK2(d0, d1, d);
            // bit-min == fminf for non-negative floats
            du[2 * j]     = umin(du[2 * j],     __float_as_uint(d0));
            du[2 * j + 1] = umin(du[2 * j + 1], __float_as_uint(d1));
            bmax = umax(bmax, umax(du[2 * j], du[2 * j + 1]));
        }
        // first local index attaining bmax (descending keeps smallest j)
        int bi = 0x7fffffff;
#pragma unroll
        for (int j = 7; j >= 0; j--)
            if (du[j] == bmax) bi = tid + (j << 10);

        const unsigned wmax = __reduce_max_sync(0xffffffffu, bmax);
        const int      wmin = __reduce_min_sync(
            0xffffffffu, (bmax == wmax) ? bi : 0x7fffffff);
        if (lane == 0) { s_wv[par][warp] = wmax; s_wi[par][warp] = wmin; }
        __syncthreads();  // the only barrier per iteration

        const unsigned v = s_wv[par][lane];
        const int      i = s_wi[par][lane];
        const unsigned gm = __reduce_max_sync(0xffffffffu, v);
        far = __reduce_min_sync(0xffffffffu, (v == gm) ? i : 0x7fffffff);
    }
}

// ---------------------------------------------------------------------------
// KNN + gather + center: one CTA per (b, g) center. d2 math bit-identical to
// R4/R5. Keys are sign-flip sortable uint32 (order == d2 order, all floats).
// Chunk-min: warp-per-chunk, conflict-free lanes. Selection: 32 passes in
// warp 0; index finding via ballot+ffs (first occurrence == lowest offset,
// exact top_k tie order with contiguous chunks).
// ---------------------------------------------------------------------------
__global__ void __launch_bounds__(256) knn_kernel(
    const float* __restrict__ pts, const float* __restrict__ center_in,
    float* __restrict__ nbr_out) {
    __shared__ __align__(16) unsigned s_key[N_];
    __shared__ unsigned s_cmin[64];
    __shared__ int      s_sel[K_];
    __shared__ float    s_ctr[3];

    const int bg   = blockIdx.x;
    const int b    = bg >> 9;  // / G_
    const int tid  = threadIdx.x;
    const int lane = tid & 31;
    const int warp = tid >> 5;

    if (tid < 3) s_ctr[tid] = center_in[(size_t)bg * 3 + tid];
    __syncthreads();
    const float c0 = s_ctr[0], c1 = s_ctr[1], c2 = s_ctr[2];
    const float cc = sq3_fma(c0, c1, c2);

    const float* base = pts + (size_t)b * N_ * C_;
    for (int n = tid; n < N_; n += 256) {
        const float2 xy = *(const float2*)(base + (size_t)n * C_);
        const float x0 = xy.x, x1 = xy.y;
        const float x2 = base[(size_t)n * C_ + 2];
        const float xx = sq3_fma(x0, x1, x2);
        float dot = __fmul_rn(c0, x0);
        dot = __fmaf_rn(c1, x1, dot);
        dot = __fmaf_rn(c2, x2, dot);
        const float d2 = __fsub_rn(__fadd_rn(cc, xx), __fmul_rn(2.0f, dot));
        const unsigned bits = __float_as_uint(d2);
        s_key[n] = (bits & 0x80000000u) ? ~bits : (bits | 0x80000000u);
    }
    __syncthreads();

    // chunk minima: warp w handles chunks [8w, 8w+8); lanes conflict-free
#pragma unroll
    for (int t = 0; t < 8; t++) {
        const int c = (warp << 3) + t;
        const unsigned base_i = (unsigned)(c << 7) + lane;
        const unsigned m =
            umin(umin(s_key[base_i], s_key[base_i + 32]),
                 umin(s_key[base_i + 64], s_key[base_i + 96]));
        const unsigned cm = __reduce_min_sync(0xffffffffu, m);
        if (lane == 0) s_cmin[c] = cm;
    }
    __syncthreads();

    if (warp == 0) {
        for (int k = 0; k < K_; k++) {
            const unsigned a  = s_cmin[lane];
            const unsigned bb = s_cmin[lane + 32];
            const unsigned g  = __reduce_min_sync(0xffffffffu, umin(a, bb));
            // lowest chunk holding g (chunks contiguous -> index order)
            const unsigned ba = __ballot_sync(0xffffffffu, a == g);
            const unsigned bB = __ballot_sync(0xffffffffu, bb == g);
            const unsigned c  = ba ? (unsigned)(__ffs(ba) - 1)
                                   : (unsigned)(__ffs(bB) - 1 + 32);

            const unsigned bi = (c << 7) + lane;
            unsigned v0 = s_key[bi];
            unsigned v1 = s_key[bi + 32];
            unsigned v2 = s_key[bi + 64];
            unsigned v3 = s_key[bi + 96];
            const unsigned m0 = __ballot_sync(0xffffffffu, v0 == g);
            const unsigned m1 = __ballot_sync(0xffffffffu, v1 == g);
            const unsigned m2 = __ballot_sync(0xffffffffu, v2 == g);
            const unsigned m3 = __ballot_sync(0xffffffffu, v3 == g);
            unsigned prel;
            if (m0)      prel = (unsigned)(__ffs(m0) - 1);
            else if (m1) prel = (unsigned)(__ffs(m1) - 1 + 32);
            else if (m2) prel = (unsigned)(__ffs(m2) - 1 + 64);
            else         prel = (unsigned)(__ffs(m3) - 1 + 96);
            const unsigned p = (c << 7) + prel;

            // poison winner in registers, recompute chunk min
            if (lane + 0u  == prel) v0 = 0xffffffffu;
            if (lane + 32u == prel) v1 = 0xffffffffu;
            if (lane + 64u == prel) v2 = 0xffffffffu;
            if (lane + 96u == prel) v3 = 0xffffffffu;
            const unsigned nm = __reduce_min_sync(
                0xffffffffu, umin(umin(v0, v1), umin(v2, v3)));
            if (lane == 0) {
                s_sel[k]  = (int)p;
                s_key[p]  = 0xffffffffu;  // for future rescans of this chunk
                s_cmin[c] = nm;
            }
            __syncwarp();
        }
    }
    __syncthreads();

    // Gather neighborhoods and center the xyz channels.
    if (tid < K_ * C_) {
        const int k = tid / C_;
        const int c = tid % C_;
        const int i = s_sel[k];
        float v = base[(size_t)i * C_ + c];
        if (c < 3) v = __fsub_rn(v, s_ctr[c]);
        nbr_out[((size_t)bg * K_ + k) * C_ + c] = v;
    }
}

extern "C" void kernel_launch(void* const* d_in, const int* in_sizes, int n_in,
                              void* d_out, int out_size) {
    const float* pts = (const float*)d_in[0];
    float* out = (float*)d_out;
    // output layout: neighborhood (B,G,K,C) flattened, then center (B,G,3)
    float* center_out = out + (size_t)B_ * G_ * K_ * C_;

    fps_kernel<<<B_, 1024>>>(pts, center_out);
    knn_kernel<<<B_ * G_, 256>>>(pts, center_out, out);
}